// round 1
// baseline (speedup 1.0000x reference)
#include <cuda_runtime.h>
#include <stdint.h>

#define N_FFT  4096
#define LOG2N  12
#define NBINS  2049     // rfft bins
#define NMICS  8
#define BATCH  16
#define NPAIR  28
#define NLAG   81       // lags -40..40

__device__ float2 g_W[BATCH * NMICS * NBINS];            // whitened spectra
__device__ float  g_cc[NPAIR * NLAG * BATCH];            // cc table [p][t][b]
__device__ unsigned long long g_best[BATCH];             // packed argmax per batch

__device__ __forceinline__ int brev12(int i) { return __brev((unsigned)i) >> 20; }

// ---------------------------------------------------------------------------
// Kernel 1: forward 4096-pt FFT of each (batch, mic) signal + PHAT whitening.
// One block per signal (128 blocks). Radix-2 DIT in shared memory.
// ---------------------------------------------------------------------------
__global__ void __launch_bounds__(256) k_fft_whiten(const float* __restrict__ sig)
{
    __shared__ float2 s[N_FFT];
    const int tid = threadIdx.x;
    const float* x = sig + (size_t)blockIdx.x * N_FFT;

    for (int i = tid; i < N_FFT; i += 256)
        s[brev12(i)] = make_float2(x[i], 0.0f);
    __syncthreads();

    for (int st = 1; st <= LOG2N; ++st) {
        const int half = 1 << (st - 1);
        const float ang0 = -3.14159265358979f / (float)half;  // forward: e^{-i*}
        for (int j = tid; j < N_FFT / 2; j += 256) {
            int k  = j & (half - 1);
            int i1 = ((j >> (st - 1)) << st) + k;
            int i2 = i1 + half;
            float sn, c;
            __sincosf(ang0 * (float)k, &sn, &c);
            float2 a = s[i1], b = s[i2];
            float tr = c * b.x - sn * b.y;
            float ti = c * b.y + sn * b.x;
            s[i1] = make_float2(a.x + tr, a.y + ti);
            s[i2] = make_float2(a.x - tr, a.y - ti);
        }
        __syncthreads();
    }

    // whiten: W = S / |S|   (per-channel PHAT factorization)
    float2* w = g_W + (size_t)blockIdx.x * NBINS;
    for (int k = tid; k < NBINS; k += 256) {
        float2 v = s[k];
        float inv = rsqrtf(v.x * v.x + v.y * v.y + 1e-24f);
        w[k] = make_float2(v.x * inv, v.y * inv);
    }
}

// ---------------------------------------------------------------------------
// Kernel 2: per (batch,pair) cross-spectrum + inverse FFT, TWO pairs packed
// per complex iFFT (Hermitian spectra -> real cc). 224 blocks.
// Extract 81 lags (-40..40). Global 1/N scale dropped (argmax-invariant).
// ---------------------------------------------------------------------------
__global__ void __launch_bounds__(256) k_xcorr(const int* __restrict__ comb)
{
    __shared__ float2 s[N_FFT];
    const int tid = threadIdx.x;
    const int q0 = blockIdx.x * 2, q1 = q0 + 1;
    const int b0 = q0 / NPAIR, p0 = q0 % NPAIR;
    const int b1 = q1 / NPAIR, p1 = q1 % NPAIR;

    const float2* Wa0 = g_W + (size_t)(b0 * NMICS + comb[2 * p0    ]) * NBINS;
    const float2* Wb0 = g_W + (size_t)(b0 * NMICS + comb[2 * p0 + 1]) * NBINS;
    const float2* Wa1 = g_W + (size_t)(b1 * NMICS + comb[2 * p1    ]) * NBINS;
    const float2* Wb1 = g_W + (size_t)(b1 * NMICS + comb[2 * p1 + 1]) * NBINS;

    // Z[k] = X1[k] + i*X2[k]; Hermitian extension; store bit-reversed.
    for (int k = tid; k < NBINS; k += 256) {
        float2 a0 = Wa0[k], c0 = Wb0[k];
        float x1r = a0.x * c0.x + a0.y * c0.y;
        float x1i = a0.y * c0.x - a0.x * c0.y;   // X1 = Wa0 * conj(Wb0)
        float2 a1 = Wa1[k], c1 = Wb1[k];
        float x2r = a1.x * c1.x + a1.y * c1.y;
        float x2i = a1.y * c1.x - a1.x * c1.y;   // X2 = Wa1 * conj(Wb1)

        s[brev12(k)] = make_float2(x1r - x2i, x1i + x2r);
        if (k > 0 && k < N_FFT / 2) {
            // Z[N-k] = conj(X1[k]) + i*conj(X2[k])
            s[brev12(N_FFT - k)] = make_float2(x1r + x2i, x2r - x1i);
        }
    }
    __syncthreads();

    for (int st = 1; st <= LOG2N; ++st) {
        const int half = 1 << (st - 1);
        const float ang0 = 3.14159265358979f / (float)half;   // inverse: e^{+i*}
        for (int j = tid; j < N_FFT / 2; j += 256) {
            int k  = j & (half - 1);
            int i1 = ((j >> (st - 1)) << st) + k;
            int i2 = i1 + half;
            float sn, c;
            __sincosf(ang0 * (float)k, &sn, &c);
            float2 a = s[i1], b = s[i2];
            float tr = c * b.x - sn * b.y;
            float ti = c * b.y + sn * b.x;
            s[i1] = make_float2(a.x + tr, a.y + ti);
            s[i2] = make_float2(a.x - tr, a.y - ti);
        }
        __syncthreads();
    }

    // cc[t] for t in 0..80 <-> lag (t-40) mod 4096. Real part = pair q0, imag = q1.
    for (int t = tid; t < NLAG; t += 256) {
        int idx = (t + (N_FFT - 40)) & (N_FFT - 1);
        float2 v = s[idx];
        g_cc[(p0 * NLAG + t) * BATCH + b0] = v.x;
        g_cc[(p1 * NLAG + t) * BATCH + b1] = v.y;
    }
}

// ---------------------------------------------------------------------------
// Kernel 3: SRP accumulation over pairs + global argmax per batch.
// ---------------------------------------------------------------------------
__global__ void k_reset()
{
    if (threadIdx.x < BATCH) g_best[threadIdx.x] = 0ull;
}

__device__ __forceinline__ unsigned int fkey(float f)
{
    unsigned int b = __float_as_uint(f);
    return (b & 0x80000000u) ? ~b : (b | 0x80000000u);   // order-preserving
}

__global__ void __launch_bounds__(256) k_srp(const int* __restrict__ tau, int G)
{
    __shared__ unsigned long long sbest[BATCH];
    if (threadIdx.x < BATCH) sbest[threadIdx.x] = 0ull;
    __syncthreads();

    int g = blockIdx.x * 256 + threadIdx.x;
    if (g < G) {
        float pw[BATCH];
        #pragma unroll
        for (int b = 0; b < BATCH; ++b) pw[b] = 0.0f;

        const int4* trow = (const int4*)(tau + (size_t)g * NPAIR);  // 28 = 7*int4
        #pragma unroll
        for (int pc = 0; pc < NPAIR / 4; ++pc) {
            int4 tv = trow[pc];
            int ts[4] = { tv.x, tv.y, tv.z, tv.w };
            #pragma unroll
            for (int e = 0; e < 4; ++e) {
                int p = pc * 4 + e;
                const float4* row = (const float4*)(g_cc + (p * NLAG + ts[e]) * BATCH);
                float4 r0 = row[0], r1 = row[1], r2 = row[2], r3 = row[3];
                pw[0]  += r0.x; pw[1]  += r0.y; pw[2]  += r0.z; pw[3]  += r0.w;
                pw[4]  += r1.x; pw[5]  += r1.y; pw[6]  += r1.z; pw[7]  += r1.w;
                pw[8]  += r2.x; pw[9]  += r2.y; pw[10] += r2.z; pw[11] += r2.w;
                pw[12] += r3.x; pw[13] += r3.y; pw[14] += r3.z; pw[15] += r3.w;
            }
        }
        #pragma unroll
        for (int b = 0; b < BATCH; ++b) {
            // high 32: orderable power key; low 32: ~g so ties pick smallest g
            unsigned long long pk =
                ((unsigned long long)fkey(pw[b]) << 32) | (unsigned int)(~(unsigned int)g);
            atomicMax(&sbest[b], pk);
        }
    }
    __syncthreads();
    if (threadIdx.x < BATCH) atomicMax(&g_best[threadIdx.x], sbest[threadIdx.x]);
}

// ---------------------------------------------------------------------------
// Kernel 4: decode argmax -> output grid point minus centroid.
// ---------------------------------------------------------------------------
__global__ void k_final(const float* __restrict__ grid_x,
                        const float* __restrict__ cen,
                        float* __restrict__ out)
{
    int b = threadIdx.x;
    if (b < BATCH) {
        unsigned int inv = (unsigned int)(g_best[b] & 0xFFFFFFFFull);
        unsigned int idx = ~inv;
        #pragma unroll
        for (int j = 0; j < 3; ++j)
            out[b * 3 + j] = grid_x[(size_t)idx * 3 + j] - cen[j];
    }
}

// ---------------------------------------------------------------------------
extern "C" void kernel_launch(void* const* d_in, const int* in_sizes, int n_in,
                              void* d_out, int out_size)
{
    const float* signal = (const float*)d_in[0];
    const float* grid_x = (const float*)d_in[1];
    const int*   tau    = (const int*)d_in[2];
    const int*   comb   = (const int*)d_in[3];
    const float* cen    = (const float*)d_in[4];

    const int G = in_sizes[1] / 3;   // grid points

    k_fft_whiten<<<BATCH * NMICS, 256>>>(signal);
    k_xcorr<<<BATCH * NPAIR / 2, 256>>>(comb);
    k_reset<<<1, 32>>>();
    k_srp<<<(G + 255) / 256, 256>>>(tau, G);
    k_final<<<1, 32>>>(grid_x, cen, (float*)d_out);
}

// round 2
// speedup vs baseline: 1.1714x; 1.1714x over previous
#include <cuda_runtime.h>
#include <stdint.h>

#define N_FFT  4096
#define LOG2N  12
#define NBINS  2049     // rfft bins
#define NMICS  8
#define BATCH  16
#define NPAIR  28
#define NLAG   81       // lags -40..40

__device__ float2 g_W[BATCH * NMICS * NBINS];            // whitened spectra
__device__ float  g_cc[NPAIR * NLAG * BATCH];            // cc table [p][t][b]
__device__ unsigned long long g_best[BATCH];             // packed argmax per batch

__device__ __forceinline__ int brev12(int i) { return __brev((unsigned)i) >> 20; }

// ---------------------------------------------------------------------------
// Kernel 1: forward 4096-pt FFT of each (batch, mic) signal + PHAT whitening.
// One block per signal (128 blocks). Radix-2 DIT in shared memory.
// ---------------------------------------------------------------------------
__global__ void __launch_bounds__(256) k_fft_whiten(const float* __restrict__ sig)
{
    __shared__ float2 s[N_FFT];
    const int tid = threadIdx.x;
    const float* x = sig + (size_t)blockIdx.x * N_FFT;

    for (int i = tid; i < N_FFT; i += 256)
        s[brev12(i)] = make_float2(x[i], 0.0f);
    __syncthreads();

    for (int st = 1; st <= LOG2N; ++st) {
        const int half = 1 << (st - 1);
        const float ang0 = -3.14159265358979f / (float)half;  // forward: e^{-i*}
        for (int j = tid; j < N_FFT / 2; j += 256) {
            int k  = j & (half - 1);
            int i1 = ((j >> (st - 1)) << st) + k;
            int i2 = i1 + half;
            float sn, c;
            __sincosf(ang0 * (float)k, &sn, &c);
            float2 a = s[i1], b = s[i2];
            float tr = c * b.x - sn * b.y;
            float ti = c * b.y + sn * b.x;
            s[i1] = make_float2(a.x + tr, a.y + ti);
            s[i2] = make_float2(a.x - tr, a.y - ti);
        }
        __syncthreads();
    }

    // whiten: W = S / |S|   (per-channel PHAT factorization)
    float2* w = g_W + (size_t)blockIdx.x * NBINS;
    for (int k = tid; k < NBINS; k += 256) {
        float2 v = s[k];
        float inv = rsqrtf(v.x * v.x + v.y * v.y + 1e-24f);
        w[k] = make_float2(v.x * inv, v.y * inv);
    }
}

// ---------------------------------------------------------------------------
// Kernel 2: per (batch,pair) cross-spectrum + inverse FFT, TWO pairs packed
// per complex iFFT (Hermitian spectra -> real cc). 224 blocks.
// Extract 81 lags (-40..40). Global 1/N scale dropped (argmax-invariant).
// ---------------------------------------------------------------------------
__global__ void __launch_bounds__(256) k_xcorr(const int* __restrict__ comb)
{
    __shared__ float2 s[N_FFT];
    const int tid = threadIdx.x;
    const int q0 = blockIdx.x * 2, q1 = q0 + 1;
    const int b0 = q0 / NPAIR, p0 = q0 % NPAIR;
    const int b1 = q1 / NPAIR, p1 = q1 % NPAIR;

    const float2* Wa0 = g_W + (size_t)(b0 * NMICS + comb[2 * p0    ]) * NBINS;
    const float2* Wb0 = g_W + (size_t)(b0 * NMICS + comb[2 * p0 + 1]) * NBINS;
    const float2* Wa1 = g_W + (size_t)(b1 * NMICS + comb[2 * p1    ]) * NBINS;
    const float2* Wb1 = g_W + (size_t)(b1 * NMICS + comb[2 * p1 + 1]) * NBINS;

    // Z[k] = X1[k] + i*X2[k]; Hermitian extension; store bit-reversed.
    for (int k = tid; k < NBINS; k += 256) {
        float2 a0 = Wa0[k], c0 = Wb0[k];
        float x1r = a0.x * c0.x + a0.y * c0.y;
        float x1i = a0.y * c0.x - a0.x * c0.y;   // X1 = Wa0 * conj(Wb0)
        float2 a1 = Wa1[k], c1 = Wb1[k];
        float x2r = a1.x * c1.x + a1.y * c1.y;
        float x2i = a1.y * c1.x - a1.x * c1.y;   // X2 = Wa1 * conj(Wb1)

        s[brev12(k)] = make_float2(x1r - x2i, x1i + x2r);
        if (k > 0 && k < N_FFT / 2) {
            // Z[N-k] = conj(X1[k]) + i*conj(X2[k])
            s[brev12(N_FFT - k)] = make_float2(x1r + x2i, x2r - x1i);
        }
    }
    __syncthreads();

    for (int st = 1; st <= LOG2N; ++st) {
        const int half = 1 << (st - 1);
        const float ang0 = 3.14159265358979f / (float)half;   // inverse: e^{+i*}
        for (int j = tid; j < N_FFT / 2; j += 256) {
            int k  = j & (half - 1);
            int i1 = ((j >> (st - 1)) << st) + k;
            int i2 = i1 + half;
            float sn, c;
            __sincosf(ang0 * (float)k, &sn, &c);
            float2 a = s[i1], b = s[i2];
            float tr = c * b.x - sn * b.y;
            float ti = c * b.y + sn * b.x;
            s[i1] = make_float2(a.x + tr, a.y + ti);
            s[i2] = make_float2(a.x - tr, a.y - ti);
        }
        __syncthreads();
    }

    // cc[t] for t in 0..80 <-> lag (t-40) mod 4096. Real part = pair q0, imag = q1.
    for (int t = tid; t < NLAG; t += 256) {
        int idx = (t + (N_FFT - 40)) & (N_FFT - 1);
        float2 v = s[idx];
        g_cc[(p0 * NLAG + t) * BATCH + b0] = v.x;
        g_cc[(p1 * NLAG + t) * BATCH + b1] = v.y;
    }
}

// ---------------------------------------------------------------------------
// Kernel 3: SRP accumulation + argmax. 4 threads per grid point (4 batches
// each, one float4 per gather) -> ~4x block count vs round 1, fixing the
// occupancy ceiling (was 123 blocks on 148 SMs). Warp-level key pre-reduction
// cuts shared atomics 8x.
// ---------------------------------------------------------------------------
__global__ void k_reset()
{
    if (threadIdx.x < BATCH) g_best[threadIdx.x] = 0ull;
}

__device__ __forceinline__ unsigned int fkey(float f)
{
    unsigned int b = __float_as_uint(f);
    return (b & 0x80000000u) ? ~b : (b | 0x80000000u);   // order-preserving
}

__global__ void __launch_bounds__(256) k_srp(const int* __restrict__ tau, int G)
{
    __shared__ unsigned long long sbest[BATCH];
    if (threadIdx.x < BATCH) sbest[threadIdx.x] = 0ull;
    __syncthreads();

    const int tIdx = blockIdx.x * 256 + threadIdx.x;
    const int g    = tIdx >> 2;          // grid point
    const int bq   = threadIdx.x & 3;    // batch quarter: batches [bq*4, bq*4+4)

    unsigned long long pk[4] = {0ull, 0ull, 0ull, 0ull};

    if (g < G) {
        float4 pw = make_float4(0.0f, 0.0f, 0.0f, 0.0f);
        const int4* trow = (const int4*)(tau + (size_t)g * NPAIR);  // 28 = 7*int4
        #pragma unroll
        for (int pc = 0; pc < NPAIR / 4; ++pc) {
            int4 tv = trow[pc];
            int ts[4] = { tv.x, tv.y, tv.z, tv.w };
            #pragma unroll
            for (int e = 0; e < 4; ++e) {
                int p = pc * 4 + e;
                float4 r = *(const float4*)(g_cc + (p * NLAG + ts[e]) * BATCH + bq * 4);
                pw.x += r.x; pw.y += r.y; pw.z += r.z; pw.w += r.w;
            }
        }
        const unsigned int gk = (unsigned int)(~(unsigned int)g);
        pk[0] = ((unsigned long long)fkey(pw.x) << 32) | gk;
        pk[1] = ((unsigned long long)fkey(pw.y) << 32) | gk;
        pk[2] = ((unsigned long long)fkey(pw.z) << 32) | gk;
        pk[3] = ((unsigned long long)fkey(pw.w) << 32) | gk;
    }

    // reduce across the 8 lanes that share the same batch quarter (lane&3)
    #pragma unroll
    for (int off = 4; off < 32; off <<= 1) {
        #pragma unroll
        for (int i = 0; i < 4; ++i) {
            unsigned long long o = __shfl_xor_sync(0xFFFFFFFFu, pk[i], off);
            if (o > pk[i]) pk[i] = o;
        }
    }
    if ((threadIdx.x & 31) < 4) {
        #pragma unroll
        for (int i = 0; i < 4; ++i)
            atomicMax(&sbest[bq * 4 + i], pk[i]);
    }
    __syncthreads();
    if (threadIdx.x < BATCH) atomicMax(&g_best[threadIdx.x], sbest[threadIdx.x]);
}

// ---------------------------------------------------------------------------
// Kernel 4: decode argmax -> output grid point minus centroid.
// ---------------------------------------------------------------------------
__global__ void k_final(const float* __restrict__ grid_x,
                        const float* __restrict__ cen,
                        float* __restrict__ out)
{
    int b = threadIdx.x;
    if (b < BATCH) {
        unsigned int inv = (unsigned int)(g_best[b] & 0xFFFFFFFFull);
        unsigned int idx = ~inv;
        #pragma unroll
        for (int j = 0; j < 3; ++j)
            out[b * 3 + j] = grid_x[(size_t)idx * 3 + j] - cen[j];
    }
}

// ---------------------------------------------------------------------------
extern "C" void kernel_launch(void* const* d_in, const int* in_sizes, int n_in,
                              void* d_out, int out_size)
{
    const float* signal = (const float*)d_in[0];
    const float* grid_x = (const float*)d_in[1];
    const int*   tau    = (const int*)d_in[2];
    const int*   comb   = (const int*)d_in[3];
    const float* cen    = (const float*)d_in[4];

    const int G = in_sizes[1] / 3;   // grid points

    k_fft_whiten<<<BATCH * NMICS, 256>>>(signal);
    k_xcorr<<<BATCH * NPAIR / 2, 256>>>(comb);
    k_reset<<<1, 32>>>();
    int thr4 = 4 * G;
    k_srp<<<(thr4 + 255) / 256, 256>>>(tau, G);
    k_final<<<1, 32>>>(grid_x, cen, (float*)d_out);
}

// round 3
// speedup vs baseline: 1.3044x; 1.1135x over previous
#include <cuda_runtime.h>
#include <stdint.h>

#define N_FFT  4096
#define NBINS  2049     // rfft bins
#define NMICS  8
#define BATCH  16
#define NPAIR  28
#define NLAG   81       // lags -40..40

__device__ float2 g_W[BATCH * NMICS * NBINS];            // whitened spectra
__device__ float  g_cc[NPAIR * NLAG * BATCH];            // cc table [p][t][b]
__device__ unsigned long long g_best[BATCH];             // packed argmax per batch

// base-4 digit reversal of a 12-bit index: bit-reverse, then swap adjacent bits
__device__ __forceinline__ int dr12(int i)
{
    unsigned x = __brev((unsigned)i) >> 20;
    return (int)(((x & 0xAAAu) >> 1) | ((x & 0x555u) << 1));
}

__device__ __forceinline__ float2 cmul(float2 a, float2 b)
{
    return make_float2(a.x * b.x - a.y * b.y, a.x * b.y + a.y * b.x);
}

// ---------------------------------------------------------------------------
// In-place 4096-pt radix-4 FFT over shared memory. Input must be stored
// base-4 digit-reversed; output in natural order. DIR=-1 forward, +1 inverse.
// One sincos per butterfly; W^2, W^3 by complex multiplication (FMA pipe).
// 256 threads: 6 stages x 4 butterflies/thread.
// ---------------------------------------------------------------------------
template<int DIR>
__device__ __forceinline__ void fft4096_r4(float2* s, int tid)
{
    #pragma unroll
    for (int st = 0; st < 6; ++st) {
        const int L = 1 << (2 * st);
        #pragma unroll
        for (int u = 0; u < 4; ++u) {
            int j    = tid + u * 256;
            int k    = j & (L - 1);
            int base = ((j >> (2 * st)) << (2 * st + 2)) + k;

            float2 b0 = s[base];
            float2 a1 = s[base + L];
            float2 a2 = s[base + 2 * L];
            float2 a3 = s[base + 3 * L];

            float2 b1, b2, b3;
            if (st == 0) {           // twiddles are all 1 at stage 0
                b1 = a1; b2 = a2; b3 = a3;
            } else {
                float ang = (float)DIR * 6.283185307179586f * (float)k / (float)(4 * L);
                float sn, cs;
                __sincosf(ang, &sn, &cs);
                float2 w1 = make_float2(cs, sn);
                float2 w2 = cmul(w1, w1);
                float2 w3 = cmul(w2, w1);
                b1 = cmul(a1, w1);
                b2 = cmul(a2, w2);
                b3 = cmul(a3, w3);
            }

            float2 t0 = make_float2(b0.x + b2.x, b0.y + b2.y);
            float2 t1 = make_float2(b0.x - b2.x, b0.y - b2.y);
            float2 t2 = make_float2(b1.x + b3.x, b1.y + b3.y);
            float2 t3 = make_float2(b1.x - b3.x, b1.y - b3.y);

            s[base]         = make_float2(t0.x + t2.x, t0.y + t2.y);
            s[base + 2 * L] = make_float2(t0.x - t2.x, t0.y - t2.y);
            // X1 = t1 - i*DIRSIGN... : forward (DIR=-1) X1 = t1 - i t3, X3 = t1 + i t3
            s[base + L]     = make_float2(t1.x - (float)DIR * t3.y, t1.y + (float)DIR * t3.x);
            s[base + 3 * L] = make_float2(t1.x + (float)DIR * t3.y, t1.y - (float)DIR * t3.x);
        }
        __syncthreads();
    }
}

// ---------------------------------------------------------------------------
// Kernel 1: two-for-one forward FFT + PHAT whitening.
// Pack mic pair (2m, 2m+1) of one batch as z = x0 + i*x1 -> one complex FFT
// yields both spectra via Hermitian split. 64 blocks.
// ---------------------------------------------------------------------------
__global__ void __launch_bounds__(256) k_fft_whiten(const float* __restrict__ sig)
{
    __shared__ float2 s[N_FFT];
    const int tid = threadIdx.x;
    const int b  = blockIdx.x >> 2;        // batch
    const int mp = blockIdx.x & 3;         // mic pair
    const float* x0 = sig + (size_t)(b * NMICS + 2 * mp) * N_FFT;
    const float* x1 = x0 + N_FFT;

    for (int i = tid; i < N_FFT; i += 256)
        s[dr12(i)] = make_float2(x0[i], x1[i]);
    __syncthreads();

    fft4096_r4<-1>(s, tid);

    float2* w0 = g_W + (size_t)(b * NMICS + 2 * mp) * NBINS;
    float2* w1 = w0 + NBINS;
    for (int k = tid; k < NBINS; k += 256) {
        float2 Zk = s[k];
        float2 Zn = s[(N_FFT - k) & (N_FFT - 1)];
        // S0 = Zk + conj(Zn);  S1 = -i*(Zk - conj(Zn))   (x2 scale dropped)
        float2 A = make_float2(Zk.x + Zn.x, Zk.y - Zn.y);
        float2 B = make_float2(Zk.y + Zn.y, Zn.x - Zk.x);
        float ia = rsqrtf(A.x * A.x + A.y * A.y + 1e-24f);
        float ib = rsqrtf(B.x * B.x + B.y * B.y + 1e-24f);
        w0[k] = make_float2(A.x * ia, A.y * ia);
        w1[k] = make_float2(B.x * ib, B.y * ib);
    }
}

// ---------------------------------------------------------------------------
// Kernel 2: cross-spectrum + inverse FFT, TWO pairs packed per complex iFFT
// (Hermitian spectra -> real cc). 224 blocks. 1/N scale dropped.
// ---------------------------------------------------------------------------
__global__ void __launch_bounds__(256) k_xcorr(const int* __restrict__ comb)
{
    __shared__ float2 s[N_FFT];
    const int tid = threadIdx.x;
    const int q0 = blockIdx.x * 2, q1 = q0 + 1;
    const int b0 = q0 / NPAIR, p0 = q0 % NPAIR;
    const int b1 = q1 / NPAIR, p1 = q1 % NPAIR;

    const float2* Wa0 = g_W + (size_t)(b0 * NMICS + comb[2 * p0    ]) * NBINS;
    const float2* Wb0 = g_W + (size_t)(b0 * NMICS + comb[2 * p0 + 1]) * NBINS;
    const float2* Wa1 = g_W + (size_t)(b1 * NMICS + comb[2 * p1    ]) * NBINS;
    const float2* Wb1 = g_W + (size_t)(b1 * NMICS + comb[2 * p1 + 1]) * NBINS;

    // Z[k] = X1[k] + i*X2[k]; Hermitian extension; store digit-reversed.
    for (int k = tid; k < NBINS; k += 256) {
        float2 a0 = Wa0[k], c0 = Wb0[k];
        float x1r = a0.x * c0.x + a0.y * c0.y;
        float x1i = a0.y * c0.x - a0.x * c0.y;   // X1 = Wa0 * conj(Wb0)
        float2 a1 = Wa1[k], c1 = Wb1[k];
        float x2r = a1.x * c1.x + a1.y * c1.y;
        float x2i = a1.y * c1.x - a1.x * c1.y;   // X2 = Wa1 * conj(Wb1)

        s[dr12(k)] = make_float2(x1r - x2i, x1i + x2r);
        if (k > 0 && k < N_FFT / 2) {
            // Z[N-k] = conj(X1[k]) + i*conj(X2[k])
            s[dr12(N_FFT - k)] = make_float2(x1r + x2i, x2r - x1i);
        }
    }
    __syncthreads();

    fft4096_r4<1>(s, tid);

    // cc[t] for t in 0..80 <-> lag (t-40) mod 4096. Real = pair q0, imag = q1.
    for (int t = tid; t < NLAG; t += 256) {
        int idx = (t + (N_FFT - 40)) & (N_FFT - 1);
        float2 v = s[idx];
        g_cc[(p0 * NLAG + t) * BATCH + b0] = v.x;
        g_cc[(p1 * NLAG + t) * BATCH + b1] = v.y;
    }
}

// ---------------------------------------------------------------------------
// Kernel 3: SRP accumulation + argmax. 4 threads per grid point.
// ---------------------------------------------------------------------------
__global__ void k_reset()
{
    if (threadIdx.x < BATCH) g_best[threadIdx.x] = 0ull;
}

__device__ __forceinline__ unsigned int fkey(float f)
{
    unsigned int b = __float_as_uint(f);
    return (b & 0x80000000u) ? ~b : (b | 0x80000000u);   // order-preserving
}

__global__ void __launch_bounds__(256) k_srp(const int* __restrict__ tau, int G)
{
    __shared__ unsigned long long sbest[BATCH];
    if (threadIdx.x < BATCH) sbest[threadIdx.x] = 0ull;
    __syncthreads();

    const int tIdx = blockIdx.x * 256 + threadIdx.x;
    const int g    = tIdx >> 2;          // grid point
    const int bq   = threadIdx.x & 3;    // batch quarter

    unsigned long long pk[4] = {0ull, 0ull, 0ull, 0ull};

    if (g < G) {
        float4 pw = make_float4(0.0f, 0.0f, 0.0f, 0.0f);
        const int4* trow = (const int4*)(tau + (size_t)g * NPAIR);  // 28 = 7*int4
        #pragma unroll
        for (int pc = 0; pc < NPAIR / 4; ++pc) {
            int4 tv = trow[pc];
            int ts[4] = { tv.x, tv.y, tv.z, tv.w };
            #pragma unroll
            for (int e = 0; e < 4; ++e) {
                int p = pc * 4 + e;
                float4 r = *(const float4*)(g_cc + (p * NLAG + ts[e]) * BATCH + bq * 4);
                pw.x += r.x; pw.y += r.y; pw.z += r.z; pw.w += r.w;
            }
        }
        const unsigned int gk = (unsigned int)(~(unsigned int)g);
        pk[0] = ((unsigned long long)fkey(pw.x) << 32) | gk;
        pk[1] = ((unsigned long long)fkey(pw.y) << 32) | gk;
        pk[2] = ((unsigned long long)fkey(pw.z) << 32) | gk;
        pk[3] = ((unsigned long long)fkey(pw.w) << 32) | gk;
    }

    // reduce across the 8 lanes sharing a batch quarter
    #pragma unroll
    for (int off = 4; off < 32; off <<= 1) {
        #pragma unroll
        for (int i = 0; i < 4; ++i) {
            unsigned long long o = __shfl_xor_sync(0xFFFFFFFFu, pk[i], off);
            if (o > pk[i]) pk[i] = o;
        }
    }
    if ((threadIdx.x & 31) < 4) {
        #pragma unroll
        for (int i = 0; i < 4; ++i)
            atomicMax(&sbest[bq * 4 + i], pk[i]);
    }
    __syncthreads();
    if (threadIdx.x < BATCH) atomicMax(&g_best[threadIdx.x], sbest[threadIdx.x]);
}

// ---------------------------------------------------------------------------
// Kernel 4: decode argmax -> output grid point minus centroid.
// ---------------------------------------------------------------------------
__global__ void k_final(const float* __restrict__ grid_x,
                        const float* __restrict__ cen,
                        float* __restrict__ out)
{
    int b = threadIdx.x;
    if (b < BATCH) {
        unsigned int idx = ~(unsigned int)(g_best[b] & 0xFFFFFFFFull);
        #pragma unroll
        for (int j = 0; j < 3; ++j)
            out[b * 3 + j] = grid_x[(size_t)idx * 3 + j] - cen[j];
    }
}

// ---------------------------------------------------------------------------
extern "C" void kernel_launch(void* const* d_in, const int* in_sizes, int n_in,
                              void* d_out, int out_size)
{
    const float* signal = (const float*)d_in[0];
    const float* grid_x = (const float*)d_in[1];
    const int*   tau    = (const int*)d_in[2];
    const int*   comb   = (const int*)d_in[3];
    const float* cen    = (const float*)d_in[4];

    const int G = in_sizes[1] / 3;   // grid points

    k_fft_whiten<<<BATCH * NMICS / 2, 256>>>(signal);
    k_xcorr<<<BATCH * NPAIR / 2, 256>>>(comb);
    k_reset<<<1, 32>>>();
    k_srp<<<(4 * G + 255) / 256, 256>>>(tau, G);
    k_final<<<1, 32>>>(grid_x, cen, (float*)d_out);
}

// round 4
// speedup vs baseline: 1.4859x; 1.1391x over previous
#include <cuda_runtime.h>
#include <stdint.h>

#define N_FFT  4096
#define NBINS  2049
#define NMICS  8
#define BATCH  16
#define NPAIR  28
#define NLAG   81

// padded smem index: provably conflict-free for all access patterns used here
#define SP(i) ((i) + ((i) >> 4) + ((i) >> 8))
#define SMEM_PAD 4368          // SP(4095)=4365 -> round up

__device__ float2 g_W[BATCH * NMICS * NBINS];        // whitened spectra (natural order)
__device__ float  g_cc[NPAIR * NLAG * BATCH];        // cc table [p][t][b]
__device__ unsigned long long g_best[BATCH];
__device__ float2 g_tw3[1360 * 3];                   // stage twiddles (W,W^2,W^3), forward sign

// base-4 digit reversal of 12-bit index (involution)
__device__ __forceinline__ int dr12(int i)
{
    unsigned x = __brev((unsigned)i) >> 20;
    return (int)(((x & 0xAAAu) >> 1) | ((x & 0x555u) << 1));
}

__device__ __forceinline__ float2 cmul(float2 a, float2 b)
{
    return make_float2(a.x * b.x - a.y * b.y, a.x * b.y + a.y * b.x);
}

// ---------------------------------------------------------------------------
// init: build twiddle tables (once per call) + zero argmax slots.
// stage Q=1024 at off 0, Q=256 at 1024, Q=64 at 1280, Q=16 at 1344.
// ---------------------------------------------------------------------------
__global__ void k_init()
{
    int gid = blockIdx.x * 256 + threadIdx.x;
    if (gid == 0) {
        #pragma unroll
        for (int b = 0; b < BATCH; ++b) g_best[b] = 0ull;
    }
    if (gid < 1360) {
        int Q, k;
        if      (gid < 1024) { Q = 1024; k = gid; }
        else if (gid < 1280) { Q = 256;  k = gid - 1024; }
        else if (gid < 1344) { Q = 64;   k = gid - 1280; }
        else                 { Q = 16;   k = gid - 1344; }
        float th = -3.14159265358979323846f * (float)k / (2.0f * (float)Q);
        #pragma unroll
        for (int m = 1; m <= 3; ++m) {
            float sn, cs;
            sincosf(th * (float)m, &sn, &cs);
            g_tw3[gid * 3 + (m - 1)] = make_float2(cs, sn);
        }
    }
}

// ---------------------------------------------------------------------------
// In-place 4096-pt radix-4 DIF FFT over padded shared memory.
// Natural-order input, base-4 digit-reversed output.
// 4 table-twiddle stages (Q=1024..16) + fused in-register radix-16 tail.
// DIR=-1 forward, +1 inverse.
// ---------------------------------------------------------------------------
template<int DIR>
__device__ __forceinline__ void fft4096_dif(float2* s, int tid)
{
    const float sg = (DIR < 0) ? 1.0f : -1.0f;   // sign of the -i factor / twiddle conj

    const int OFF[4] = {0, 1024, 1280, 1344};
    #pragma unroll
    for (int st = 0; st < 4; ++st) {
        const int lg = 10 - 2 * st;              // log2(Q)
        const int Q  = 1 << lg;
        #pragma unroll
        for (int u = 0; u < 4; ++u) {
            int j    = tid + u * 256;
            int k    = j & (Q - 1);
            int base = ((j >> lg) << (lg + 2)) + k;

            float2 a0 = s[SP(base)];
            float2 a1 = s[SP(base + Q)];
            float2 a2 = s[SP(base + 2 * Q)];
            float2 a3 = s[SP(base + 3 * Q)];

            float2 A = make_float2(a0.x + a2.x, a0.y + a2.y);
            float2 B = make_float2(a0.x - a2.x, a0.y - a2.y);
            float2 C = make_float2(a1.x + a3.x, a1.y + a3.y);
            float2 D = make_float2(a1.x - a3.x, a1.y - a3.y);

            float2 y0 = make_float2(A.x + C.x, A.y + C.y);
            float2 y1 = make_float2(B.x + sg * D.y, B.y - sg * D.x);
            float2 y2 = make_float2(A.x - C.x, A.y - C.y);
            float2 y3 = make_float2(B.x - sg * D.y, B.y + sg * D.x);

            const float2* t3 = g_tw3 + (size_t)(OFF[st] + k) * 3;
            float2 w1 = t3[0], w2 = t3[1], w3 = t3[2];
            if (DIR > 0) { w1.y = -w1.y; w2.y = -w2.y; w3.y = -w3.y; }

            s[SP(base)]         = y0;
            s[SP(base + Q)]     = cmul(y1, w1);
            s[SP(base + 2 * Q)] = cmul(y2, w2);
            s[SP(base + 3 * Q)] = cmul(y3, w3);
        }
        __syncthreads();
    }

    // fused radix-16 (stages Q=4, Q=1): 16 contiguous elements per thread,
    // twiddles are 16th-root compile-time constants.
    {
        const float CS[10] = { 1.f,  0.92387953f,  0.70710678f,  0.38268343f,  0.f,
                              -0.38268343f, -0.70710678f, -0.92387953f, -1.f, -0.92387953f};
        const float SN[10] = { 0.f, -0.38268343f, -0.70710678f, -0.92387953f, -1.f,
                              -0.92387953f, -0.70710678f, -0.38268343f,  0.f,  0.38268343f};
        float2 v[16];
        const int e0 = 16 * tid;
        #pragma unroll
        for (int m = 0; m < 16; ++m) v[m] = s[SP(e0 + m)];

        #pragma unroll
        for (int m = 0; m < 4; ++m) {           // stage Q=4
            float2 p = v[m], q = v[m + 4], r = v[m + 8], w = v[m + 12];
            float2 A = make_float2(p.x + r.x, p.y + r.y);
            float2 B = make_float2(p.x - r.x, p.y - r.y);
            float2 C = make_float2(q.x + w.x, q.y + w.y);
            float2 D = make_float2(q.x - w.x, q.y - w.y);
            float2 y0 = make_float2(A.x + C.x, A.y + C.y);
            float2 y1 = make_float2(B.x + sg * D.y, B.y - sg * D.x);
            float2 y2 = make_float2(A.x - C.x, A.y - C.y);
            float2 y3 = make_float2(B.x - sg * D.y, B.y + sg * D.x);
            float2 w1 = make_float2(CS[m],     sg * SN[m]);
            float2 w2 = make_float2(CS[2 * m], sg * SN[2 * m]);
            float2 w3 = make_float2(CS[3 * m], sg * SN[3 * m]);
            v[m]      = y0;
            v[m + 4]  = cmul(y1, w1);
            v[m + 8]  = cmul(y2, w2);
            v[m + 12] = cmul(y3, w3);
        }
        #pragma unroll
        for (int h = 0; h < 4; ++h) {           // stage Q=1 (no twiddle)
            float2 p = v[4*h], q = v[4*h+1], r = v[4*h+2], w = v[4*h+3];
            float2 A = make_float2(p.x + r.x, p.y + r.y);
            float2 B = make_float2(p.x - r.x, p.y - r.y);
            float2 C = make_float2(q.x + w.x, q.y + w.y);
            float2 D = make_float2(q.x - w.x, q.y - w.y);
            v[4*h]   = make_float2(A.x + C.x, A.y + C.y);
            v[4*h+1] = make_float2(B.x + sg * D.y, B.y - sg * D.x);
            v[4*h+2] = make_float2(A.x - C.x, A.y - C.y);
            v[4*h+3] = make_float2(B.x - sg * D.y, B.y + sg * D.x);
        }
        #pragma unroll
        for (int m = 0; m < 16; ++m) s[SP(e0 + m)] = v[m];
    }
    __syncthreads();
}

// ---------------------------------------------------------------------------
// Kernel 1: two-for-one forward FFT + PHAT whitening. 64 blocks.
// Natural contiguous fill (DIF); spectra extracted at dr positions; g_W natural.
// ---------------------------------------------------------------------------
__global__ void __launch_bounds__(256) k_fft_whiten(const float* __restrict__ sig)
{
    __shared__ float2 s[SMEM_PAD];
    const int tid = threadIdx.x;
    const int b  = blockIdx.x >> 2;
    const int mp = blockIdx.x & 3;
    const float* x0 = sig + (size_t)(b * NMICS + 2 * mp) * N_FFT;
    const float* x1 = x0 + N_FFT;

    for (int i = tid; i < N_FFT; i += 256)
        s[SP(i)] = make_float2(x0[i], x1[i]);
    __syncthreads();

    fft4096_dif<-1>(s, tid);

    float2* w0 = g_W + (size_t)(b * NMICS + 2 * mp) * NBINS;
    float2* w1 = w0 + NBINS;
    for (int k = tid; k < NBINS; k += 256) {
        float2 Zk = s[SP(dr12(k))];
        float2 Zn = s[SP(dr12((N_FFT - k) & (N_FFT - 1)))];
        float2 A = make_float2(Zk.x + Zn.x, Zk.y - Zn.y);
        float2 B = make_float2(Zk.y + Zn.y, Zn.x - Zk.x);
        float ia = rsqrtf(A.x * A.x + A.y * A.y + 1e-24f);
        float ib = rsqrtf(B.x * B.x + B.y * B.y + 1e-24f);
        w0[k] = make_float2(A.x * ia, A.y * ia);
        w1[k] = make_float2(B.x * ib, B.y * ib);
    }
}

// ---------------------------------------------------------------------------
// Kernel 2: cross-spectrum + inverse DIF FFT, two pairs packed per iFFT.
// Natural fill (conflict-free); 81 lag reads at dr slots. 224 blocks.
// ---------------------------------------------------------------------------
__global__ void __launch_bounds__(256) k_xcorr(const int* __restrict__ comb)
{
    __shared__ float2 s[SMEM_PAD];
    const int tid = threadIdx.x;
    const int q0 = blockIdx.x * 2, q1 = q0 + 1;
    const int b0 = q0 / NPAIR, p0 = q0 % NPAIR;
    const int b1 = q1 / NPAIR, p1 = q1 % NPAIR;

    const float2* Wa0 = g_W + (size_t)(b0 * NMICS + comb[2 * p0    ]) * NBINS;
    const float2* Wb0 = g_W + (size_t)(b0 * NMICS + comb[2 * p0 + 1]) * NBINS;
    const float2* Wa1 = g_W + (size_t)(b1 * NMICS + comb[2 * p1    ]) * NBINS;
    const float2* Wb1 = g_W + (size_t)(b1 * NMICS + comb[2 * p1 + 1]) * NBINS;

    // Z[n] = X1[n] + i*X2[n] natural order; Hermitian mirror to n>2048.
    for (int k = tid; k <= N_FFT / 2; k += 256) {
        float2 a0 = Wa0[k], c0 = Wb0[k];
        float x1r = a0.x * c0.x + a0.y * c0.y;
        float x1i = a0.y * c0.x - a0.x * c0.y;
        float2 a1 = Wa1[k], c1 = Wb1[k];
        float x2r = a1.x * c1.x + a1.y * c1.y;
        float x2i = a1.y * c1.x - a1.x * c1.y;

        s[SP(k)] = make_float2(x1r - x2i, x1i + x2r);
        if (k > 0 && k < N_FFT / 2)
            s[SP(N_FFT - k)] = make_float2(x1r + x2i, x2r - x1i);
    }
    __syncthreads();

    fft4096_dif<1>(s, tid);

    for (int t = tid; t < NLAG; t += 256) {
        int idx = (t + (N_FFT - 40)) & (N_FFT - 1);
        float2 v = s[SP(dr12(idx))];
        g_cc[(p0 * NLAG + t) * BATCH + b0] = v.x;
        g_cc[(p1 * NLAG + t) * BATCH + b1] = v.y;
    }
}

// ---------------------------------------------------------------------------
// Kernel 3: SRP accumulation + argmax. 8 threads per grid point (2 batches
// each, float2 gathers) -> ~982 blocks for occupancy/issue headroom.
// ---------------------------------------------------------------------------
__device__ __forceinline__ unsigned int fkey(float f)
{
    unsigned int b = __float_as_uint(f);
    return (b & 0x80000000u) ? ~b : (b | 0x80000000u);
}

__global__ void __launch_bounds__(256) k_srp(const int* __restrict__ tau, int G)
{
    __shared__ unsigned long long sbest[BATCH];
    if (threadIdx.x < BATCH) sbest[threadIdx.x] = 0ull;
    __syncthreads();

    const int tIdx = blockIdx.x * 256 + threadIdx.x;
    const int g    = tIdx >> 3;
    const int bp   = threadIdx.x & 7;       // batches 2bp, 2bp+1

    unsigned long long k0 = 0ull, k1 = 0ull;

    if (g < G) {
        float2 pw = make_float2(0.0f, 0.0f);
        const int4* trow = (const int4*)(tau + (size_t)g * NPAIR);
        #pragma unroll
        for (int pc = 0; pc < NPAIR / 4; ++pc) {
            int4 tv = trow[pc];
            int ts[4] = { tv.x, tv.y, tv.z, tv.w };
            #pragma unroll
            for (int e = 0; e < 4; ++e) {
                int p = pc * 4 + e;
                float2 r = *(const float2*)(g_cc + (p * NLAG + ts[e]) * BATCH + bp * 2);
                pw.x += r.x; pw.y += r.y;
            }
        }
        const unsigned int gk = ~(unsigned int)g;
        k0 = ((unsigned long long)fkey(pw.x) << 32) | gk;
        k1 = ((unsigned long long)fkey(pw.y) << 32) | gk;
    }

    // reduce lanes sharing the same bp (xor offsets 8, 16)
    #pragma unroll
    for (int off = 8; off < 32; off <<= 1) {
        unsigned long long o0 = __shfl_xor_sync(0xFFFFFFFFu, k0, off);
        unsigned long long o1 = __shfl_xor_sync(0xFFFFFFFFu, k1, off);
        if (o0 > k0) k0 = o0;
        if (o1 > k1) k1 = o1;
    }
    if ((threadIdx.x & 31) < 8) {
        atomicMax(&sbest[bp * 2],     k0);
        atomicMax(&sbest[bp * 2 + 1], k1);
    }
    __syncthreads();
    if (threadIdx.x < BATCH) atomicMax(&g_best[threadIdx.x], sbest[threadIdx.x]);
}

// ---------------------------------------------------------------------------
__global__ void k_final(const float* __restrict__ grid_x,
                        const float* __restrict__ cen,
                        float* __restrict__ out)
{
    int b = threadIdx.x;
    if (b < BATCH) {
        unsigned int idx = ~(unsigned int)(g_best[b] & 0xFFFFFFFFull);
        #pragma unroll
        for (int j = 0; j < 3; ++j)
            out[b * 3 + j] = grid_x[(size_t)idx * 3 + j] - cen[j];
    }
}

// ---------------------------------------------------------------------------
extern "C" void kernel_launch(void* const* d_in, const int* in_sizes, int n_in,
                              void* d_out, int out_size)
{
    const float* signal = (const float*)d_in[0];
    const float* grid_x = (const float*)d_in[1];
    const int*   tau    = (const int*)d_in[2];
    const int*   comb   = (const int*)d_in[3];
    const float* cen    = (const float*)d_in[4];

    const int G = in_sizes[1] / 3;

    k_init<<<6, 256>>>();
    k_fft_whiten<<<BATCH * NMICS / 2, 256>>>(signal);
    k_xcorr<<<BATCH * NPAIR / 2, 256>>>(comb);
    k_srp<<<(8 * G + 255) / 256, 256>>>(tau, G);
    k_final<<<1, 32>>>(grid_x, cen, (float*)d_out);
}